// round 9
// baseline (speedup 1.0000x reference)
#include <cuda_runtime.h>
#include <math_constants.h>

#define FULL_MASK 0xFFFFFFFFu
#define INF_BITS  0x7f800000u

// x: (32, 2, 513, 2048) fp32. channel 0 = magnitude, channel 1 = phase.
// rows = 32*513 = 16416, row length 2048.
// R9 = R8 (one row / 64-thr block, 2 warps, sorted-6 + REDUX.MIN extraction,
// ~1% wave tail) with the extraction critical path trimmed:
//  - all tied lanes pop simultaneously via FSELs (no ffs/ballot on the chain)
//  - exact tie handling via take-weighted sum (k-counted), off the chain.

// Branchless insert into sorted list a0<=...<=a5 (keep 6 smallest).
#define INS6(a0,a1,a2,a3,a4,a5,sv) do { float s_ = (sv); \
    a5 = fminf(a5, fmaxf(a4, s_));                       \
    a4 = fminf(a4, fmaxf(a3, s_));                       \
    a3 = fminf(a3, fmaxf(a2, s_));                       \
    a2 = fminf(a2, fmaxf(a1, s_));                       \
    a1 = fminf(a1, fmaxf(a0, s_));                       \
    a0 = fminf(a0, s_); } while (0)

#define INSA(sv) INS6(m0,m1,m2,m3,m4,m5,sv)
#define INSB(sv) INS6(n0,n1,n2,n3,n4,n5,sv)

__global__ __launch_bounds__(64, 16)   // <=64 regs -> 16 blocks -> 32 warps/SM
void spectral_sub_kernel(const float* __restrict__ x, float* __restrict__ out)
{
    __shared__ float s_lists[6][32];   // warp1's per-lane sorted-6
    __shared__ float s_noise;

    const int lane = threadIdx.x & 31;
    const int warp = threadIdx.x >> 5;           // 0 or 1
    const int row  = blockIdx.x;                 // [0, 16416)

    const int b = row / 513;
    const int f = row - b * 513;
    const size_t moff = (size_t)(b * 1026 + f) * 2048;   // ((b*2+0)*513+f)*2048
    const float4* __restrict__ magv = (const float4*)(x + moff);
    const float4* __restrict__ phv  = (const float4*)(x + moff + (size_t)513 * 2048);
    float4* __restrict__ outr = (float4*)(out + moff);
    float4* __restrict__ outi = (float4*)(out + moff + (size_t)513 * 2048);

    const int base = warp * 8;                   // this warp's half: float4 idx [base, base+8)

    // ---- Phase A: per-lane sorted-6 over this warp's 32 values/lane ----
    float m0 = CUDART_INF_F, m1 = CUDART_INF_F, m2 = CUDART_INF_F,
          m3 = CUDART_INF_F, m4 = CUDART_INF_F, m5 = CUDART_INF_F;
    float n0 = CUDART_INF_F, n1 = CUDART_INF_F, n2 = CUDART_INF_F,
          n3 = CUDART_INF_F, n4 = CUDART_INF_F, n5 = CUDART_INF_F;
    {
        float4 d[8];
        #pragma unroll
        for (int c = 0; c < 8; ++c)               // 8 LDG.128 batched (MLP=8)
            d[c] = magv[(base + c) * 32 + lane];
        #pragma unroll
        for (int c = 0; c < 4; ++c) {             // two independent chains
            float4 a = d[c], e = d[c + 4];
            INSA(a.x * a.x);  INSB(e.x * e.x);
            INSA(a.y * a.y);  INSB(e.y * e.y);
            INSA(a.z * a.z);  INSB(e.z * e.z);
            INSA(a.w * a.w);  INSB(e.w * e.w);
        }
        INSA(n0); INSA(n1); INSA(n2); INSA(n3); INSA(n4); INSA(n5);
    }

    if (warp == 1) {
        s_lists[0][lane] = m0; s_lists[1][lane] = m1; s_lists[2][lane] = m2;
        s_lists[3][lane] = m3; s_lists[4][lane] = m4; s_lists[5][lane] = m5;
    }
    __syncthreads();

    // ---- prefetch own half's pass-2 batch 0 (in flight during extraction) ----
    float4 pm[4], pp[4];
    #pragma unroll
    for (int c = 0; c < 4; ++c) {
        pm[c] = magv[(base + c) * 32 + lane];
        pp[c] = __ldcs(&phv[(base + c) * 32 + lane]);
    }

    if (warp == 0) {
        // merge warp1's lists: lane slot i now covers the FULL row column i
        INSA(s_lists[0][lane]); INSA(s_lists[1][lane]); INSA(s_lists[2][lane]);
        INSA(s_lists[3][lane]); INSA(s_lists[4][lane]); INSA(s_lists[5][lane]);

        // ---- extraction: ascending pops of the warp-wide minimum ----
        // squares >= 0: float bits order-isomorphic to u32.
        // All tied lanes pop at once (FSELs; ballot NOT on the critical path);
        // sum weights the popped value by take = min(#tied, remaining k) -> exact.
        float sum = 0.0f;
        int   k   = 32;
        #pragma unroll 1
        for (int iter = 0; iter < 32; ++iter) {
            unsigned u = __float_as_uint(m0);
            unsigned w = __reduce_min_sync(FULL_MASK, u);     // REDUX.MIN
            const bool pop = (u == w);
            // off-critical-path bookkeeping (exact tie multiplicity)
            unsigned bal = __ballot_sync(FULL_MASK, pop);
            int take = __popc(bal); take = (take < k) ? take : k;
            sum = fmaf((float)take, __uint_as_float(w), sum);
            k -= take;
            // critical path: predicated shift-down of the sorted list
            float t0 = pop ? m1 : m0;
            m1 = pop ? m2 : m1;
            m2 = pop ? m3 : m2;
            m3 = pop ? m4 : m3;
            m4 = pop ? m5 : m4;
            m5 = pop ? CUDART_INF_F : m5;
            m0 = t0;
            if (pop && __float_as_uint(m0) == INF_BITS) {
                // exact rebuild (rare): next-6 of this lane's FULL column > w
                const float t = __uint_as_float(w);
                #pragma unroll
                for (int c = 0; c < 16; ++c) {
                    float4 dv = magv[c * 32 + lane];          // L2-hot reload
                    float s;
                    s = dv.x * dv.x; s = (s > t) ? s : CUDART_INF_F; INSA(s);
                    s = dv.y * dv.y; s = (s > t) ? s : CUDART_INF_F; INSA(s);
                    s = dv.z * dv.z; s = (s > t) ? s : CUDART_INF_F; INSA(s);
                    s = dv.w * dv.w; s = (s > t) ? s : CUDART_INF_F; INSA(s);
                }
            }
        }
        if (lane == 0) s_noise = sum * (1.0f / 32.0f);
    }
    __syncthreads();
    const float noise = s_noise;

    // ---- Pass 2 on own half: mag re-read (L1/L2-hot) + streamed phase ----
    #pragma unroll
    for (int s = 0; s < 2; ++s) {
        float4 mm[4], ph[4];
        if (s == 0) {
            #pragma unroll
            for (int c = 0; c < 4; ++c) { mm[c] = pm[c]; ph[c] = pp[c]; }
        } else {
            #pragma unroll
            for (int c = 0; c < 4; ++c) {             // 8 LDGs batched (MLP=8)
                mm[c] = magv[(base + 4 + c) * 32 + lane];
                ph[c] = __ldcs(&phv[(base + 4 + c) * 32 + lane]);
            }
        }
        #pragma unroll
        for (int c = 0; c < 4; ++c) {
            const int o = (base + s * 4 + c) * 32 + lane;
            float4 re, im;
            float m, sn, cs;
            m = fmaxf(mm[c].x - noise, 0.0f); __sincosf(ph[c].x, &sn, &cs); re.x = m*cs; im.x = m*sn;
            m = fmaxf(mm[c].y - noise, 0.0f); __sincosf(ph[c].y, &sn, &cs); re.y = m*cs; im.y = m*sn;
            m = fmaxf(mm[c].z - noise, 0.0f); __sincosf(ph[c].z, &sn, &cs); re.z = m*cs; im.z = m*sn;
            m = fmaxf(mm[c].w - noise, 0.0f); __sincosf(ph[c].w, &sn, &cs); re.w = m*cs; im.w = m*sn;
            __stcs(&outr[o], re);
            __stcs(&outi[o], im);
        }
    }
}

extern "C" void kernel_launch(void* const* d_in, const int* in_sizes, int n_in,
                              void* d_out, int out_size)
{
    const float* x = (const float*)d_in[0];
    // d_in[1] = n_avg (int32, fixed at 32 for this problem; algorithm specialized for k==32)
    float* out = (float*)d_out;

    // one row per 64-thread block: 16416 blocks, 6.93 waves of 2368 slots (~1% tail)
    spectral_sub_kernel<<<16416, 64>>>(x, out);
}

// round 10
// speedup vs baseline: 1.0004x; 1.0004x over previous
#include <cuda_runtime.h>
#include <math_constants.h>

#define FULL_MASK 0xFFFFFFFFu
#define INF_BITS  0x7f800000u

// x: (32, 2, 513, 2048) fp32. channel 0 = magnitude, channel 1 = phase.
// rows = 32*513 = 16416, row length 2048.
// R10 = R9 (one row / 64-thr block, sorted-6 + trimmed REDUX.MIN extraction,
// ~1% wave tail) with REDUNDANT DUAL EXTRACTION: both warps exchange sorted-6
// lists through smem after ONE barrier, then each merges + extracts
// independently (bit-identical noise) and proceeds straight to pass 2 on its
// half. Removes warp1's ~1.3K-cycle barrier stall, the 2nd __syncthreads,
// and the s_noise broadcast.

// Branchless insert into sorted list a0<=...<=a5 (keep 6 smallest).
#define INS6(a0,a1,a2,a3,a4,a5,sv) do { float s_ = (sv); \
    a5 = fminf(a5, fmaxf(a4, s_));                       \
    a4 = fminf(a4, fmaxf(a3, s_));                       \
    a3 = fminf(a3, fmaxf(a2, s_));                       \
    a2 = fminf(a2, fmaxf(a1, s_));                       \
    a1 = fminf(a1, fmaxf(a0, s_));                       \
    a0 = fminf(a0, s_); } while (0)

#define INSA(sv) INS6(m0,m1,m2,m3,m4,m5,sv)
#define INSB(sv) INS6(n0,n1,n2,n3,n4,n5,sv)

__global__ __launch_bounds__(64, 16)   // <=64 regs -> 16 blocks -> 32 warps/SM
void spectral_sub_kernel(const float* __restrict__ x, float* __restrict__ out)
{
    __shared__ float s_lists[2][6][32];  // each warp's per-lane sorted-6

    const int lane = threadIdx.x & 31;
    const int warp = threadIdx.x >> 5;           // 0 or 1
    const int row  = blockIdx.x;                 // [0, 16416)

    const int b = row / 513;
    const int f = row - b * 513;
    const size_t moff = (size_t)(b * 1026 + f) * 2048;   // ((b*2+0)*513+f)*2048
    const float4* __restrict__ magv = (const float4*)(x + moff);
    const float4* __restrict__ phv  = (const float4*)(x + moff + (size_t)513 * 2048);
    float4* __restrict__ outr = (float4*)(out + moff);
    float4* __restrict__ outi = (float4*)(out + moff + (size_t)513 * 2048);

    const int base = warp * 8;                   // this warp's half: float4 idx [base, base+8)

    // ---- Phase A: per-lane sorted-6 over this warp's 32 values/lane ----
    float m0 = CUDART_INF_F, m1 = CUDART_INF_F, m2 = CUDART_INF_F,
          m3 = CUDART_INF_F, m4 = CUDART_INF_F, m5 = CUDART_INF_F;
    float n0 = CUDART_INF_F, n1 = CUDART_INF_F, n2 = CUDART_INF_F,
          n3 = CUDART_INF_F, n4 = CUDART_INF_F, n5 = CUDART_INF_F;
    {
        float4 d[8];
        #pragma unroll
        for (int c = 0; c < 8; ++c)               // 8 LDG.128 batched (MLP=8)
            d[c] = magv[(base + c) * 32 + lane];
        #pragma unroll
        for (int c = 0; c < 4; ++c) {             // two independent chains
            float4 a = d[c], e = d[c + 4];
            INSA(a.x * a.x);  INSB(e.x * e.x);
            INSA(a.y * a.y);  INSB(e.y * e.y);
            INSA(a.z * a.z);  INSB(e.z * e.z);
            INSA(a.w * a.w);  INSB(e.w * e.w);
        }
        INSA(n0); INSA(n1); INSA(n2); INSA(n3); INSA(n4); INSA(n5);
    }

    // publish own list, one barrier, then both warps proceed independently
    s_lists[warp][0][lane] = m0; s_lists[warp][1][lane] = m1;
    s_lists[warp][2][lane] = m2; s_lists[warp][3][lane] = m3;
    s_lists[warp][4][lane] = m4; s_lists[warp][5][lane] = m5;
    __syncthreads();

    // ---- prefetch own half's pass-2 batch 0 (in flight during extraction) ----
    float4 pm[4], pp[4];
    #pragma unroll
    for (int c = 0; c < 4; ++c) {
        pm[c] = magv[(base + c) * 32 + lane];
        pp[c] = __ldcs(&phv[(base + c) * 32 + lane]);
    }

    // merge the OTHER warp's lists: lane slot i now covers the FULL row column i
    {
        const int o = warp ^ 1;
        INSA(s_lists[o][0][lane]); INSA(s_lists[o][1][lane]); INSA(s_lists[o][2][lane]);
        INSA(s_lists[o][3][lane]); INSA(s_lists[o][4][lane]); INSA(s_lists[o][5][lane]);
    }

    // ---- extraction (both warps, redundant & bit-identical) ----
    // squares >= 0: float bits order-isomorphic to u32.
    // All tied lanes pop at once (FSELs; ballot off the critical path);
    // sum weights the popped value by take = min(#tied, remaining k) -> exact.
    float sum = 0.0f;
    int   k   = 32;
    #pragma unroll 1
    for (int iter = 0; iter < 32; ++iter) {
        unsigned u = __float_as_uint(m0);
        unsigned w = __reduce_min_sync(FULL_MASK, u);     // REDUX.MIN
        const bool pop = (u == w);
        unsigned bal = __ballot_sync(FULL_MASK, pop);     // off-chain bookkeeping
        int take = __popc(bal); take = (take < k) ? take : k;
        sum = fmaf((float)take, __uint_as_float(w), sum);
        k -= take;
        // critical path: predicated shift-down of the sorted list
        float t0 = pop ? m1 : m0;
        m1 = pop ? m2 : m1;
        m2 = pop ? m3 : m2;
        m3 = pop ? m4 : m3;
        m4 = pop ? m5 : m4;
        m5 = pop ? CUDART_INF_F : m5;
        m0 = t0;
        if (pop && __float_as_uint(m0) == INF_BITS) {
            // exact rebuild (rare): next-6 of this lane's FULL column > w
            const float t = __uint_as_float(w);
            #pragma unroll
            for (int c = 0; c < 16; ++c) {
                float4 dv = magv[c * 32 + lane];          // L2-hot reload
                float s;
                s = dv.x * dv.x; s = (s > t) ? s : CUDART_INF_F; INSA(s);
                s = dv.y * dv.y; s = (s > t) ? s : CUDART_INF_F; INSA(s);
                s = dv.z * dv.z; s = (s > t) ? s : CUDART_INF_F; INSA(s);
                s = dv.w * dv.w; s = (s > t) ? s : CUDART_INF_F; INSA(s);
            }
        }
    }
    const float noise = sum * (1.0f / 32.0f);

    // ---- Pass 2 on own half: mag re-read (L1/L2-hot) + streamed phase ----
    #pragma unroll
    for (int s = 0; s < 2; ++s) {
        float4 mm[4], ph[4];
        if (s == 0) {
            #pragma unroll
            for (int c = 0; c < 4; ++c) { mm[c] = pm[c]; ph[c] = pp[c]; }
        } else {
            #pragma unroll
            for (int c = 0; c < 4; ++c) {             // 8 LDGs batched (MLP=8)
                mm[c] = magv[(base + 4 + c) * 32 + lane];
                ph[c] = __ldcs(&phv[(base + 4 + c) * 32 + lane]);
            }
        }
        #pragma unroll
        for (int c = 0; c < 4; ++c) {
            const int o = (base + s * 4 + c) * 32 + lane;
            float4 re, im;
            float m, sn, cs;
            m = fmaxf(mm[c].x - noise, 0.0f); __sincosf(ph[c].x, &sn, &cs); re.x = m*cs; im.x = m*sn;
            m = fmaxf(mm[c].y - noise, 0.0f); __sincosf(ph[c].y, &sn, &cs); re.y = m*cs; im.y = m*sn;
            m = fmaxf(mm[c].z - noise, 0.0f); __sincosf(ph[c].z, &sn, &cs); re.z = m*cs; im.z = m*sn;
            m = fmaxf(mm[c].w - noise, 0.0f); __sincosf(ph[c].w, &sn, &cs); re.w = m*cs; im.w = m*sn;
            __stcs(&outr[o], re);
            __stcs(&outi[o], im);
        }
    }
}

extern "C" void kernel_launch(void* const* d_in, const int* in_sizes, int n_in,
                              void* d_out, int out_size)
{
    const float* x = (const float*)d_in[0];
    // d_in[1] = n_avg (int32, fixed at 32 for this problem; algorithm specialized for k==32)
    float* out = (float*)d_out;

    // one row per 64-thread block: 16416 blocks, 6.93 waves of 2368 slots (~1% tail)
    spectral_sub_kernel<<<16416, 64>>>(x, out);
}

// round 11
// speedup vs baseline: 1.0022x; 1.0019x over previous
#include <cuda_runtime.h>
#include <math_constants.h>

#define FULL_MASK 0xFFFFFFFFu
#define INF_BITS  0x7f800000u

// x: (32, 2, 513, 2048) fp32. channel 0 = magnitude, channel 1 = phase.
// rows = 32*513 = 16416, row length 2048.
// R11 = R9 (one row / 64-thr block, warp0 extracts with trimmed REDUX.MIN
// chain, ~1% wave tail) + SMEM MAG STASH: the mag row is written to smem
// during phase A (8KB/block; 16 blocks -> 128KB of the idle 228KB), so the
// pass-2 mag re-read and the rare rebuild read come from LDS (29cyc,
// conflict-free) instead of L1TEX/L2 -> removes ~134MB of L1/L2 read traffic
// and all residual DRAM re-read misses. Own-lane reads need no extra barrier;
// the cross-half rebuild read is covered by the existing __syncthreads.

// Branchless insert into sorted list a0<=...<=a5 (keep 6 smallest).
#define INS6(a0,a1,a2,a3,a4,a5,sv) do { float s_ = (sv); \
    a5 = fminf(a5, fmaxf(a4, s_));                       \
    a4 = fminf(a4, fmaxf(a3, s_));                       \
    a3 = fminf(a3, fmaxf(a2, s_));                       \
    a2 = fminf(a2, fmaxf(a1, s_));                       \
    a1 = fminf(a1, fmaxf(a0, s_));                       \
    a0 = fminf(a0, s_); } while (0)

#define INSA(sv) INS6(m0,m1,m2,m3,m4,m5,sv)
#define INSB(sv) INS6(n0,n1,n2,n3,n4,n5,sv)

__global__ __launch_bounds__(64, 16)   // <=64 regs -> 16 blocks -> 32 warps/SM
void spectral_sub_kernel(const float* __restrict__ x, float* __restrict__ out)
{
    __shared__ float4 s_mag[512];        // full mag row, 8KB
    __shared__ float  s_lists[6][32];    // warp1's per-lane sorted-6
    __shared__ float  s_noise;

    const int lane = threadIdx.x & 31;
    const int warp = threadIdx.x >> 5;           // 0 or 1
    const int row  = blockIdx.x;                 // [0, 16416)

    const int b = row / 513;
    const int f = row - b * 513;
    const size_t moff = (size_t)(b * 1026 + f) * 2048;   // ((b*2+0)*513+f)*2048
    const float4* __restrict__ magv = (const float4*)(x + moff);
    const float4* __restrict__ phv  = (const float4*)(x + moff + (size_t)513 * 2048);
    float4* __restrict__ outr = (float4*)(out + moff);
    float4* __restrict__ outi = (float4*)(out + moff + (size_t)513 * 2048);

    const int base = warp * 8;                   // this warp's half: float4 idx [base, base+8)

    // ---- Phase A: per-lane sorted-6 over this warp's 32 values/lane,
    //      stashing the mag row into smem on the way ----
    float m0 = CUDART_INF_F, m1 = CUDART_INF_F, m2 = CUDART_INF_F,
          m3 = CUDART_INF_F, m4 = CUDART_INF_F, m5 = CUDART_INF_F;
    float n0 = CUDART_INF_F, n1 = CUDART_INF_F, n2 = CUDART_INF_F,
          n3 = CUDART_INF_F, n4 = CUDART_INF_F, n5 = CUDART_INF_F;
    {
        float4 d[8];
        #pragma unroll
        for (int c = 0; c < 8; ++c)               // 8 LDG.128 batched (MLP=8)
            d[c] = magv[(base + c) * 32 + lane];
        #pragma unroll
        for (int c = 0; c < 8; ++c)               // stash (STS.128, conflict-free)
            s_mag[(base + c) * 32 + lane] = d[c];
        #pragma unroll
        for (int c = 0; c < 4; ++c) {             // two independent chains
            float4 a = d[c], e = d[c + 4];
            INSA(a.x * a.x);  INSB(e.x * e.x);
            INSA(a.y * a.y);  INSB(e.y * e.y);
            INSA(a.z * a.z);  INSB(e.z * e.z);
            INSA(a.w * a.w);  INSB(e.w * e.w);
        }
        INSA(n0); INSA(n1); INSA(n2); INSA(n3); INSA(n4); INSA(n5);
    }

    if (warp == 1) {
        s_lists[0][lane] = m0; s_lists[1][lane] = m1; s_lists[2][lane] = m2;
        s_lists[3][lane] = m3; s_lists[4][lane] = m4; s_lists[5][lane] = m5;
    }
    __syncthreads();   // publishes lists AND the full smem mag row

    // ---- prefetch own half's pass-2 phase batch 0 (in flight during extraction) ----
    float4 pp[4];
    #pragma unroll
    for (int c = 0; c < 4; ++c)
        pp[c] = __ldcs(&phv[(base + c) * 32 + lane]);

    if (warp == 0) {
        // merge warp1's lists: lane slot i now covers the FULL row column i
        INSA(s_lists[0][lane]); INSA(s_lists[1][lane]); INSA(s_lists[2][lane]);
        INSA(s_lists[3][lane]); INSA(s_lists[4][lane]); INSA(s_lists[5][lane]);

        // ---- extraction: ascending pops of the warp-wide minimum ----
        // squares >= 0: float bits order-isomorphic to u32.
        // Tied lanes pop together (FSELs); exact tie multiplicity via
        // take-weighted sum, off the critical path.
        float sum = 0.0f;
        int   k   = 32;
        #pragma unroll 1
        for (int iter = 0; iter < 32; ++iter) {
            unsigned u = __float_as_uint(m0);
            unsigned w = __reduce_min_sync(FULL_MASK, u);     // REDUX.MIN
            const bool pop = (u == w);
            unsigned bal = __ballot_sync(FULL_MASK, pop);     // off-chain bookkeeping
            int take = __popc(bal); take = (take < k) ? take : k;
            sum = fmaf((float)take, __uint_as_float(w), sum);
            k -= take;
            // critical path: predicated shift-down of the sorted list
            float t0 = pop ? m1 : m0;
            m1 = pop ? m2 : m1;
            m2 = pop ? m3 : m2;
            m3 = pop ? m4 : m3;
            m4 = pop ? m5 : m4;
            m5 = pop ? CUDART_INF_F : m5;
            m0 = t0;
            if (pop && __float_as_uint(m0) == INF_BITS) {
                // exact rebuild (rare): next-6 of this lane's FULL column > w,
                // read from the smem stash (post-barrier, cross-half safe)
                const float t = __uint_as_float(w);
                #pragma unroll
                for (int c = 0; c < 16; ++c) {
                    float4 dv = s_mag[c * 32 + lane];
                    float s;
                    s = dv.x * dv.x; s = (s > t) ? s : CUDART_INF_F; INSA(s);
                    s = dv.y * dv.y; s = (s > t) ? s : CUDART_INF_F; INSA(s);
                    s = dv.z * dv.z; s = (s > t) ? s : CUDART_INF_F; INSA(s);
                    s = dv.w * dv.w; s = (s > t) ? s : CUDART_INF_F; INSA(s);
                }
            }
        }
        if (lane == 0) s_noise = sum * (1.0f / 32.0f);
    }
    __syncthreads();
    const float noise = s_noise;

    // ---- Pass 2 on own half: mag from smem (LDS) + streamed phase ----
    #pragma unroll
    for (int s = 0; s < 2; ++s) {
        float4 ph[4];
        if (s == 0) {
            #pragma unroll
            for (int c = 0; c < 4; ++c) ph[c] = pp[c];
        } else {
            #pragma unroll
            for (int c = 0; c < 4; ++c)               // 4 LDGs batched
                ph[c] = __ldcs(&phv[(base + 4 + c) * 32 + lane]);
        }
        #pragma unroll
        for (int c = 0; c < 4; ++c) {
            const int o = (base + s * 4 + c) * 32 + lane;
            float4 mm = s_mag[o];                      // LDS.128, conflict-free
            float4 re, im;
            float m, sn, cs;
            m = fmaxf(mm.x - noise, 0.0f); __sincosf(ph[c].x, &sn, &cs); re.x = m*cs; im.x = m*sn;
            m = fmaxf(mm.y - noise, 0.0f); __sincosf(ph[c].y, &sn, &cs); re.y = m*cs; im.y = m*sn;
            m = fmaxf(mm.z - noise, 0.0f); __sincosf(ph[c].z, &sn, &cs); re.z = m*cs; im.z = m*sn;
            m = fmaxf(mm.w - noise, 0.0f); __sincosf(ph[c].w, &sn, &cs); re.w = m*cs; im.w = m*sn;
            __stcs(&outr[o], re);
            __stcs(&outi[o], im);
        }
    }
}

extern "C" void kernel_launch(void* const* d_in, const int* in_sizes, int n_in,
                              void* d_out, int out_size)
{
    const float* x = (const float*)d_in[0];
    // d_in[1] = n_avg (int32, fixed at 32 for this problem; algorithm specialized for k==32)
    float* out = (float*)d_out;

    // one row per 64-thread block: 16416 blocks, 6.93 waves of 2368 slots (~1% tail)
    spectral_sub_kernel<<<16416, 64>>>(x, out);
}

// round 12
// speedup vs baseline: 1.0232x; 1.0209x over previous
#include <cuda_runtime.h>
#include <math_constants.h>

#define FULL_MASK 0xFFFFFFFFu
#define INF_BITS  0x7f800000u

// x: (32, 2, 513, 2048) fp32. channel 0 = magnitude, channel 1 = phase.
// rows = 32*513 = 16416, row length 2048.
// R12 = R11 (one row / 64-thr block, smem mag stash, warp0 extracts with the
// trimmed REDUX.MIN chain, ~1% wave tail) + PHASE L2 PREFETCH: right after the
// mag LDGs, each lane issues one prefetch.global.L2 covering its warp's 4KB
// phase half (lane i -> base + i*128). The phase DRAM read overlaps the
// INS/extraction compute window; pass-2 phase loads become L2 hits.

// Branchless insert into sorted list a0<=...<=a5 (keep 6 smallest).
#define INS6(a0,a1,a2,a3,a4,a5,sv) do { float s_ = (sv); \
    a5 = fminf(a5, fmaxf(a4, s_));                       \
    a4 = fminf(a4, fmaxf(a3, s_));                       \
    a3 = fminf(a3, fmaxf(a2, s_));                       \
    a2 = fminf(a2, fmaxf(a1, s_));                       \
    a1 = fminf(a1, fmaxf(a0, s_));                       \
    a0 = fminf(a0, s_); } while (0)

#define INSA(sv) INS6(m0,m1,m2,m3,m4,m5,sv)
#define INSB(sv) INS6(n0,n1,n2,n3,n4,n5,sv)

__global__ __launch_bounds__(64, 16)   // <=64 regs -> 16 blocks -> 32 warps/SM
void spectral_sub_kernel(const float* __restrict__ x, float* __restrict__ out)
{
    __shared__ float4 s_mag[512];        // full mag row, 8KB
    __shared__ float  s_lists[6][32];    // warp1's per-lane sorted-6
    __shared__ float  s_noise;

    const int lane = threadIdx.x & 31;
    const int warp = threadIdx.x >> 5;           // 0 or 1
    const int row  = blockIdx.x;                 // [0, 16416)

    const int b = row / 513;
    const int f = row - b * 513;
    const size_t moff = (size_t)(b * 1026 + f) * 2048;   // ((b*2+0)*513+f)*2048
    const float4* __restrict__ magv = (const float4*)(x + moff);
    const float4* __restrict__ phv  = (const float4*)(x + moff + (size_t)513 * 2048);
    float4* __restrict__ outr = (float4*)(out + moff);
    float4* __restrict__ outi = (float4*)(out + moff + (size_t)513 * 2048);

    const int base = warp * 8;                   // this warp's half: float4 idx [base, base+8)

    // ---- Phase A: per-lane sorted-6 over this warp's 32 values/lane,
    //      stashing the mag row into smem on the way ----
    float m0 = CUDART_INF_F, m1 = CUDART_INF_F, m2 = CUDART_INF_F,
          m3 = CUDART_INF_F, m4 = CUDART_INF_F, m5 = CUDART_INF_F;
    float n0 = CUDART_INF_F, n1 = CUDART_INF_F, n2 = CUDART_INF_F,
          n3 = CUDART_INF_F, n4 = CUDART_INF_F, n5 = CUDART_INF_F;
    {
        float4 d[8];
        #pragma unroll
        for (int c = 0; c < 8; ++c)               // 8 LDG.128 batched (MLP=8)
            d[c] = magv[(base + c) * 32 + lane];

        // L2-prefetch this warp's 4KB phase half: lane i covers line i.
        // Phase DRAM read overlaps the INS/extraction compute window.
        {
            const char* pfb = (const char*)(phv + base * 32) + lane * 128;
            asm volatile("prefetch.global.L2 [%0];" :: "l"(pfb));
        }

        #pragma unroll
        for (int c = 0; c < 8; ++c)               // stash (STS.128, conflict-free)
            s_mag[(base + c) * 32 + lane] = d[c];
        #pragma unroll
        for (int c = 0; c < 4; ++c) {             // two independent chains
            float4 a = d[c], e = d[c + 4];
            INSA(a.x * a.x);  INSB(e.x * e.x);
            INSA(a.y * a.y);  INSB(e.y * e.y);
            INSA(a.z * a.z);  INSB(e.z * e.z);
            INSA(a.w * a.w);  INSB(e.w * e.w);
        }
        INSA(n0); INSA(n1); INSA(n2); INSA(n3); INSA(n4); INSA(n5);
    }

    if (warp == 1) {
        s_lists[0][lane] = m0; s_lists[1][lane] = m1; s_lists[2][lane] = m2;
        s_lists[3][lane] = m3; s_lists[4][lane] = m4; s_lists[5][lane] = m5;
    }
    __syncthreads();   // publishes lists AND the full smem mag row

    // ---- prefetch own half's pass-2 phase batch 0 into regs (L2-hit now) ----
    float4 pp[4];
    #pragma unroll
    for (int c = 0; c < 4; ++c)
        pp[c] = __ldcs(&phv[(base + c) * 32 + lane]);

    if (warp == 0) {
        // merge warp1's lists: lane slot i now covers the FULL row column i
        INSA(s_lists[0][lane]); INSA(s_lists[1][lane]); INSA(s_lists[2][lane]);
        INSA(s_lists[3][lane]); INSA(s_lists[4][lane]); INSA(s_lists[5][lane]);

        // ---- extraction: ascending pops of the warp-wide minimum ----
        // squares >= 0: float bits order-isomorphic to u32.
        // Tied lanes pop together (FSELs); exact tie multiplicity via
        // take-weighted sum, off the critical path.
        float sum = 0.0f;
        int   k   = 32;
        #pragma unroll 1
        for (int iter = 0; iter < 32; ++iter) {
            unsigned u = __float_as_uint(m0);
            unsigned w = __reduce_min_sync(FULL_MASK, u);     // REDUX.MIN
            const bool pop = (u == w);
            unsigned bal = __ballot_sync(FULL_MASK, pop);     // off-chain bookkeeping
            int take = __popc(bal); take = (take < k) ? take : k;
            sum = fmaf((float)take, __uint_as_float(w), sum);
            k -= take;
            // critical path: predicated shift-down of the sorted list
            float t0 = pop ? m1 : m0;
            m1 = pop ? m2 : m1;
            m2 = pop ? m3 : m2;
            m3 = pop ? m4 : m3;
            m4 = pop ? m5 : m4;
            m5 = pop ? CUDART_INF_F : m5;
            m0 = t0;
            if (pop && __float_as_uint(m0) == INF_BITS) {
                // exact rebuild (rare): next-6 of this lane's FULL column > w,
                // read from the smem stash (post-barrier, cross-half safe)
                const float t = __uint_as_float(w);
                #pragma unroll
                for (int c = 0; c < 16; ++c) {
                    float4 dv = s_mag[c * 32 + lane];
                    float s;
                    s = dv.x * dv.x; s = (s > t) ? s : CUDART_INF_F; INSA(s);
                    s = dv.y * dv.y; s = (s > t) ? s : CUDART_INF_F; INSA(s);
                    s = dv.z * dv.z; s = (s > t) ? s : CUDART_INF_F; INSA(s);
                    s = dv.w * dv.w; s = (s > t) ? s : CUDART_INF_F; INSA(s);
                }
            }
        }
        if (lane == 0) s_noise = sum * (1.0f / 32.0f);
    }
    __syncthreads();
    const float noise = s_noise;

    // ---- Pass 2 on own half: mag from smem (LDS) + phase (L2-hit) ----
    #pragma unroll
    for (int s = 0; s < 2; ++s) {
        float4 ph[4];
        if (s == 0) {
            #pragma unroll
            for (int c = 0; c < 4; ++c) ph[c] = pp[c];
        } else {
            #pragma unroll
            for (int c = 0; c < 4; ++c)               // 4 LDGs batched
                ph[c] = __ldcs(&phv[(base + 4 + c) * 32 + lane]);
        }
        #pragma unroll
        for (int c = 0; c < 4; ++c) {
            const int o = (base + s * 4 + c) * 32 + lane;
            float4 mm = s_mag[o];                      // LDS.128, conflict-free
            float4 re, im;
            float m, sn, cs;
            m = fmaxf(mm.x - noise, 0.0f); __sincosf(ph[c].x, &sn, &cs); re.x = m*cs; im.x = m*sn;
            m = fmaxf(mm.y - noise, 0.0f); __sincosf(ph[c].y, &sn, &cs); re.y = m*cs; im.y = m*sn;
            m = fmaxf(mm.z - noise, 0.0f); __sincosf(ph[c].z, &sn, &cs); re.z = m*cs; im.z = m*sn;
            m = fmaxf(mm.w - noise, 0.0f); __sincosf(ph[c].w, &sn, &cs); re.w = m*cs; im.w = m*sn;
            __stcs(&outr[o], re);
            __stcs(&outi[o], im);
        }
    }
}

extern "C" void kernel_launch(void* const* d_in, const int* in_sizes, int n_in,
                              void* d_out, int out_size)
{
    const float* x = (const float*)d_in[0];
    // d_in[1] = n_avg (int32, fixed at 32 for this problem; algorithm specialized for k==32)
    float* out = (float*)d_out;

    // one row per 64-thread block: 16416 blocks, 6.93 waves of 2368 slots (~1% tail)
    spectral_sub_kernel<<<16416, 64>>>(x, out);
}